// round 13
// baseline (speedup 1.0000x reference)
#include <cuda_runtime.h>
#include <math.h>
#include <stdint.h>

#define HIDDEN  128
#define N_NODES 50000
#define N_EDGES 600000
#define LN_EPS  1e-5f
#define APAD    132   // A-tile smem stride: conflict-free scalar frag loads
#define BPAD    136   // B-tile smem stride: conflict-free LDS.64 frag loads
#define SCAN_BLOCKS ((N_NODES + 1023) / 1024)   // 49

// Scratch (static device arrays: no allocation allowed)
__device__ uint32_t g_Ah[N_NODES * 3 * 64];    // per-node typed projections, bf16x2 packed
__device__ float g_agg[N_NODES * HIDDEN];      // B-term partial (proj epi) -> full agg
__device__ int   g_cnt[N_NODES * 4];           // per-node per-type edge counts
__device__ int   g_pos[N_NODES];               // CSR fill cursors
__device__ int   g_off[N_NODES + 1];           // CSR row offsets (block-local until + g_bsum)
__device__ int   g_csr[N_EDGES];               // packed (src<<2)|type
__device__ int   g_bsum[SCAN_BLOCKS];          // per-scan-block exclusive prefixes
__device__ float g_Wt[768 * 128];              // Wmsg^T [j][k], k perm-within-8
__device__ float g_Wut[128 * 256];             // Wupd^T [h][k], k perm-within-8

__device__ __constant__ int JT[12] = {0,1,2,3,4,5, 6,8,10, 7,9,11};

#define CPA16(sa, gp)      asm volatile("cp.async.cg.shared.global [%0],[%1],16;" :: "r"(sa), "l"(gp))
#define CPA16Z(sa, gp, sz) asm volatile("cp.async.cg.shared.global [%0],[%1],16,%2;" :: "r"(sa), "l"(gp), "r"(sz))
#define CPA_COMMIT()       asm volatile("cp.async.commit_group;")
#define CPA_WAIT(n)        asm volatile("cp.async.wait_group %0;" :: "n"(n))

#define MMA_TF32(c, a, b)                                                        \
    asm volatile(                                                                \
        "mma.sync.aligned.m16n8k8.row.col.f32.tf32.tf32.f32 "                    \
        "{%0,%1,%2,%3},{%4,%5,%6,%7},{%8,%9},{%0,%1,%2,%3};"                     \
        : "+f"((c)[0]), "+f"((c)[1]), "+f"((c)[2]), "+f"((c)[3])                 \
        : "r"((a)[0]), "r"((a)[1]), "r"((a)[2]), "r"((a)[3]),                    \
          "r"((b)[0]), "r"((b)[1]))

__device__ __forceinline__ int perm8(int k) {   // (k,k+4) pairs adjacent within 8-group
    return (k & ~7) | (((k & 3) << 1) | ((k >> 2) & 1));
}

__device__ __forceinline__ uint32_t pack_bf16(float lo, float hi) {
    uint32_t r;
    asm("cvt.rn.bf16x2.f32 %0, %1, %2;" : "=r"(r) : "f"(hi), "f"(lo));
    return r;
}

__device__ __forceinline__ float bflo(uint32_t u) { return __uint_as_float(u << 16); }
__device__ __forceinline__ float bfhi(uint32_t u) { return __uint_as_float(u & 0xffff0000u); }

// ---------------- fused prep: zero counters | transpose Wmsg | transpose Wupd ----------------
__global__ void k_prep(const float* __restrict__ Wmsg, const float* __restrict__ Wupd) {
    __shared__ float ts[32][33];
    const int b = blockIdx.x;
    const int tid = threadIdx.x;
    if (b < 128) {
        int i = b * 256 + tid;
        int stride = 128 * 256;
        for (int j = i; j < N_NODES * 4; j += stride) g_cnt[j] = 0;
        for (int j = i; j < N_NODES; j += stride) g_pos[j] = 0;
    } else if (b < 224) {
        int bb = b - 128;
        int mat = bb >> 4;
        int tile = bb & 15;
        int ti = tile >> 2, tj = tile & 3;
        int t_ = mat % 3, part = mat / 3;
        int rx = tid & 31, ry = tid >> 5;
#pragma unroll
        for (int p = 0; p < 4; p++) {
            int k = ti * 32 + ry + p * 8;
            ts[ry + p * 8][rx] = Wmsg[(t_ * 256 + part * 128 + k) * 128 + tj * 32 + rx];
        }
        __syncthreads();
#pragma unroll
        for (int p = 0; p < 4; p++) {
            int row = ry + p * 8;
            int kp = perm8(ti * 32 + rx);
            g_Wt[(part * 384 + t_ * 128 + tj * 32 + row) * 128 + kp] = ts[rx][row];
        }
    } else {
        int bb = b - 224;
        int ti = bb >> 2, tj = bb & 3;
        int rx = tid & 31, ry = tid >> 5;
#pragma unroll
        for (int p = 0; p < 4; p++)
            ts[ry + p * 8][rx] = Wupd[(ti * 32 + ry + p * 8) * 128 + tj * 32 + rx];
        __syncthreads();
#pragma unroll
        for (int p = 0; p < 4; p++) {
            int row = ry + p * 8;
            int kp = perm8(ti * 32 + rx);
            g_Wut[(tj * 32 + row) * 256 + kp] = ts[rx][row];
        }
    }
}

// ---------------- per-(dst,type) histogram ----------------
__global__ void k_hist(const int* __restrict__ ei, const int* __restrict__ et) {
    int e = blockIdx.x * blockDim.x + threadIdx.x;
    if (e >= N_EDGES) return;
    atomicAdd(&g_cnt[ei[N_EDGES + e] * 4 + et[e]], 1);
}

// ---------------- projection GEMM: A-in-regs, depth-3 cp.async pipeline (4 W buffers) --------
__global__ void __launch_bounds__(512) k_proj(const float* __restrict__ x,
                                              const float* __restrict__ bmsg) {
    extern __shared__ float sm[];
    float* xs  = sm;                    // [128][APAD]
    float* wsb = sm + 128 * APAD;       // 4 x [64][BPAD]
    const int tid = threadIdx.x;
    const int n0 = blockIdx.x * 128;
    const uint32_t xs_b = (uint32_t)__cvta_generic_to_shared(xs);
    const uint32_t ws_b = (uint32_t)__cvta_generic_to_shared(wsb);

    // prologue: x tile (group0), W tiles 0..2 (groups 1..3)
    for (int i = tid; i < 4096; i += 512) {
        int m = i >> 5, k4 = i & 31;
        int n = n0 + m;
        int sz = (n < N_NODES) ? 16 : 0;
        CPA16Z(xs_b + (m * APAD + k4 * 4) * 4, x + (size_t)n * 128 + k4 * 4, sz);
    }
    CPA_COMMIT();
#pragma unroll
    for (int pj = 0; pj < 3; pj++) {
        const float* src = g_Wt + JT[pj] * 64 * 128;
        uint32_t dst = ws_b + pj * 64 * BPAD * 4;
        for (int i = tid; i < 2048; i += 512) {
            int r = i >> 5, k4 = i & 31;
            CPA16(dst + (r * BPAD + k4 * 4) * 4, src + r * 128 + k4 * 4);
        }
        CPA_COMMIT();
    }

    const int w = tid >> 5, lane = tid & 31;
    const int gid = lane >> 2, tig = lane & 3;
    const int m0 = (w & 7) * 16;
    const int nw = (w >> 3) * 32;
    const int r0 = n0 + m0 + gid;

    // x ready (3 W groups may remain pending)
    CPA_WAIT(3);
    __syncthreads();
    uint32_t a[16][4];
    {
        const uint32_t* As = (const uint32_t*)xs;
#pragma unroll
        for (int ks = 0; ks < 16; ks++) {
            const uint32_t* ap = As + (m0 + gid) * APAD + ks * 8 + tig;
            a[ks][0] = ap[0];
            a[ks][1] = ap[8 * APAD];
            a[ks][2] = ap[4];
            a[ks][3] = ap[8 * APAD + 4];
        }
    }

    float accB[4][4];

    for (int idx = 0; idx < 12; idx++) {
        // wait until W_idx complete (2 newer W groups may stay in flight)
        if (idx <= 9)       CPA_WAIT(2);
        else if (idx == 10) CPA_WAIT(1);
        else                CPA_WAIT(0);
        __syncthreads();    // visibility + separates last iter's readers from this iter's issue

        // issue W(idx+3) AFTER the barrier (no WAR on buffer (idx+3)&3)
        if (idx + 3 < 12) {
            uint32_t dst = ws_b + ((idx + 3) & 3) * 64 * BPAD * 4;
            const float* src = g_Wt + JT[idx + 3] * 64 * 128;
            for (int i = tid; i < 2048; i += 512) {
                int r = i >> 5, k4 = i & 31;
                CPA16(dst + (r * BPAD + k4 * 4) * 4, src + r * 128 + k4 * 4);
            }
            CPA_COMMIT();
        }

        const uint32_t* Ws = (const uint32_t*)(wsb + (idx & 3) * 64 * BPAD);

        float c[4][4];
#pragma unroll
        for (int nt = 0; nt < 4; nt++)
#pragma unroll
            for (int q = 0; q < 4; q++) c[nt][q] = 0.f;

#pragma unroll
        for (int ks = 0; ks < 16; ks++) {
#pragma unroll
            for (int nt = 0; nt < 4; nt++) {
                uint2 bv = *(const uint2*)(Ws + (nw + nt * 8 + gid) * BPAD + ks * 8 + tig * 2);
                uint32_t b[2] = {bv.x, bv.y};
                MMA_TF32(c[nt], a[ks], b);
            }
        }

        int j0 = JT[idx] * 64;
        if (j0 < 384) {
#pragma unroll
            for (int nt = 0; nt < 4; nt++) {
                int col = j0 + nw + nt * 8 + tig * 2;
                uint32_t p01 = pack_bf16(c[nt][0], c[nt][1]);
                uint32_t p23 = pack_bf16(c[nt][2], c[nt][3]);
                if (r0 < N_NODES)
                    g_Ah[(size_t)r0 * 192 + (col >> 1)] = p01;
                if (r0 + 8 < N_NODES)
                    g_Ah[(size_t)(r0 + 8) * 192 + (col >> 1)] = p23;
            }
        } else {
            int jj = j0 - 384;
            int t = jj >> 7;
            int h0 = jj & 127;
            float f0 = (r0 < N_NODES)     ? (float)g_cnt[r0 * 4 + t]       : 0.f;
            float f1 = (r0 + 8 < N_NODES) ? (float)g_cnt[(r0 + 8) * 4 + t] : 0.f;
#pragma unroll
            for (int nt = 0; nt < 4; nt++) {
                int hcol = h0 + nw + nt * 8 + tig * 2;
                float2 bm = *(const float2*)(bmsg + t * 128 + hcol);
                if (t == 0) { accB[nt][0] = 0.f; accB[nt][1] = 0.f; accB[nt][2] = 0.f; accB[nt][3] = 0.f; }
                accB[nt][0] += f0 * (c[nt][0] + bm.x);
                accB[nt][1] += f0 * (c[nt][1] + bm.y);
                accB[nt][2] += f1 * (c[nt][2] + bm.x);
                accB[nt][3] += f1 * (c[nt][3] + bm.y);
                if (t == 2) {
                    if (r0 < N_NODES)
                        *(float2*)(g_agg + (size_t)r0 * 128 + hcol) = make_float2(accB[nt][0], accB[nt][1]);
                    if (r0 + 8 < N_NODES)
                        *(float2*)(g_agg + (size_t)(r0 + 8) * 128 + hcol) = make_float2(accB[nt][2], accB[nt][3]);
                }
            }
        }
    }
}

// ---------------- 2-phase parallel exclusive scan (block-local + block prefixes) -------------
__global__ void k_scan1() {
    __shared__ int wsum[32];
    const int tid = threadIdx.x, lane = tid & 31, wid = tid >> 5;
    int n = blockIdx.x * 1024 + tid;
    int v = 0;
    if (n < N_NODES) v = g_cnt[n * 4] + g_cnt[n * 4 + 1] + g_cnt[n * 4 + 2];
    int xv = v;
#pragma unroll
    for (int o = 1; o < 32; o <<= 1) {
        int y = __shfl_up_sync(0xffffffffu, xv, o);
        if (lane >= o) xv += y;
    }
    if (lane == 31) wsum[wid] = xv;
    __syncthreads();
    if (wid == 0) {
        int s = wsum[lane];
#pragma unroll
        for (int o = 1; o < 32; o <<= 1) {
            int y = __shfl_up_sync(0xffffffffu, s, o);
            if (lane >= o) s += y;
        }
        wsum[lane] = s;
    }
    __syncthreads();
    int excl = xv - v + (wid > 0 ? wsum[wid - 1] : 0);
    if (n < N_NODES) g_off[n] = excl;      // block-local exclusive prefix
    if (tid == 1023) g_bsum[blockIdx.x] = excl + v;
}

__global__ void k_scan2() {
    int run = 0;
    for (int b = 0; b < SCAN_BLOCKS; b++) {
        int t = g_bsum[b];
        g_bsum[b] = run;                   // exclusive block prefix
        run += t;
    }
}

// ---------------- CSR bucket fill (global offset = local + block prefix) ----------------
__global__ void k_fill(const int* __restrict__ ei, const int* __restrict__ et) {
    int e = blockIdx.x * blockDim.x + threadIdx.x;
    if (e >= N_EDGES) return;
    int dst = ei[N_EDGES + e];
    int p = atomicAdd(&g_pos[dst], 1);
    g_csr[g_off[dst] + g_bsum[dst >> 10] + p] = (ei[e] << 2) | et[e];
}

// ---------------- gather-aggregate: lane-prefetched indices, 4 independent gathers -----------
__global__ void k_agg() {
    int n = (blockIdx.x * blockDim.x + threadIdx.x) >> 5;
    if (n >= N_NODES) return;
    int lane = threadIdx.x & 31;
    int beg = g_off[n] + g_bsum[n >> 10];
    int end = (n + 1 == N_NODES) ? N_EDGES : (g_off[n + 1] + g_bsum[(n + 1) >> 10]);
    int deg = end - beg;
    float4 a0 = ((const float4*)g_agg)[n * 32 + lane];   // cnt-weighted B + bias partial
    float4 a1 = make_float4(0.f, 0.f, 0.f, 0.f);
    float4 a2 = make_float4(0.f, 0.f, 0.f, 0.f);
    float4 a3 = make_float4(0.f, 0.f, 0.f, 0.f);
    const uint2* Ah = (const uint2*)g_Ah;

    for (int base = 0; base < deg; base += 32) {
        int rem = deg - base;
        if (rem > 32) rem = 32;
        int my = (lane < rem) ? __ldg(&g_csr[beg + base + lane]) : 0;
        int j = 0;
        for (; j + 4 <= rem; j += 4) {
            int p0 = __shfl_sync(0xffffffffu, my, j);
            int p1 = __shfl_sync(0xffffffffu, my, j + 1);
            int p2 = __shfl_sync(0xffffffffu, my, j + 2);
            int p3 = __shfl_sync(0xffffffffu, my, j + 3);
            uint2 v0 = __ldg(Ah + (size_t)((p0 >> 2) * 3 + (p0 & 3)) * 32 + lane);
            uint2 v1 = __ldg(Ah + (size_t)((p1 >> 2) * 3 + (p1 & 3)) * 32 + lane);
            uint2 v2 = __ldg(Ah + (size_t)((p2 >> 2) * 3 + (p2 & 3)) * 32 + lane);
            uint2 v3 = __ldg(Ah + (size_t)((p3 >> 2) * 3 + (p3 & 3)) * 32 + lane);
            a0.x += bflo(v0.x); a0.y += bfhi(v0.x); a0.z += bflo(v0.y); a0.w += bfhi(v0.y);
            a1.x += bflo(v1.x); a1.y += bfhi(v1.x); a1.z += bflo(v1.y); a1.w += bfhi(v1.y);
            a2.x += bflo(v2.x); a2.y += bfhi(v2.x); a2.z += bflo(v2.y); a2.w += bfhi(v2.y);
            a3.x += bflo(v3.x); a3.y += bfhi(v3.x); a3.z += bflo(v3.y); a3.w += bfhi(v3.y);
        }
        for (; j < rem; j++) {
            int p0 = __shfl_sync(0xffffffffu, my, j);
            uint2 v0 = __ldg(Ah + (size_t)((p0 >> 2) * 3 + (p0 & 3)) * 32 + lane);
            a0.x += bflo(v0.x); a0.y += bfhi(v0.x); a0.z += bflo(v0.y); a0.w += bfhi(v0.y);
        }
    }
    a0.x += (a1.x + a2.x) + a3.x;
    a0.y += (a1.y + a2.y) + a3.y;
    a0.z += (a1.z + a2.z) + a3.z;
    a0.w += (a1.w + a2.w) + a3.w;
    float inv = 1.f / fmaxf((float)deg, 1.f);
    a0.x *= inv; a0.y *= inv; a0.z *= inv; a0.w *= inv;
    ((float4*)g_agg)[n * 32 + lane] = a0;
}

// ---------------- update GEMM (tf32, permuted W, cp.async) + fused LN/GELU/residual -----------
__global__ void __launch_bounds__(256) k_update(const float* __restrict__ x,
                                                const float* __restrict__ bupd,
                                                const float* __restrict__ gamma,
                                                const float* __restrict__ beta,
                                                float* __restrict__ out) {
    extern __shared__ float sm[];
    float* Is = sm;                 // [128][APAD]
    float* Ws = sm + 128 * APAD;    // [128][BPAD]
    const int tid = threadIdx.x;
    const int n0 = blockIdx.x * 128;
    const uint32_t is_b = (uint32_t)__cvta_generic_to_shared(Is);
    const uint32_t ws_b = (uint32_t)__cvta_generic_to_shared(Ws);
    const int w = tid >> 5, lane = tid & 31;
    const int gid = lane >> 2, tig = lane & 3;
    const int m0 = w * 16;

    float c[16][4];
#pragma unroll
    for (int nt = 0; nt < 16; nt++)
#pragma unroll
        for (int q = 0; q < 4; q++) c[nt][q] = 0.f;

    for (int kt = 0; kt < 2; kt++) {
        const float* src = kt ? g_agg : x;
        for (int i = tid; i < 4096; i += 256) {
            int m = i >> 5, k4 = i & 31;
            int n = n0 + m;
            int sz = (n < N_NODES) ? 16 : 0;
            CPA16Z(is_b + (m * APAD + k4 * 4) * 4, src + (size_t)n * 128 + k4 * 4, sz);
        }
        for (int i = tid; i < 4096; i += 256) {
            int h = i >> 5, k4 = i & 31;
            CPA16(ws_b + (h * BPAD + k4 * 4) * 4, g_Wut + h * 256 + kt * 128 + k4 * 4);
        }
        CPA_COMMIT();
        CPA_WAIT(0);
        __syncthreads();

        const uint32_t* IsU = (const uint32_t*)Is;
        const uint32_t* WsU = (const uint32_t*)Ws;
#pragma unroll
        for (int ks = 0; ks < 16; ks++) {
            int kb = ks * 8;
            uint32_t a[4];
            const uint32_t* ap = IsU + (m0 + gid) * APAD + kb + tig;
            a[0] = ap[0];
            a[1] = ap[8 * APAD];
            a[2] = ap[4];
            a[3] = ap[8 * APAD + 4];
#pragma unroll
            for (int nt = 0; nt < 16; nt++) {
                uint2 bv = *(const uint2*)(WsU + (nt * 8 + gid) * BPAD + kb + tig * 2);
                uint32_t b[2] = {bv.x, bv.y};
                MMA_TF32(c[nt], a, b);
            }
        }
        __syncthreads();
    }

    const int r0 = n0 + m0 + gid;
    const int r1 = r0 + 8;
    float s0 = 0.f, q0 = 0.f, s1 = 0.f, q1 = 0.f;
#pragma unroll
    for (int nt = 0; nt < 16; nt++) {
        int col = nt * 8 + tig * 2;
        float2 bb = *(const float2*)(bupd + col);
        float h0 = c[nt][0] + bb.x, h1 = c[nt][1] + bb.y;
        float h2 = c[nt][2] + bb.x, h3 = c[nt][3] + bb.y;
        c[nt][0] = h0; c[nt][1] = h1; c[nt][2] = h2; c[nt][3] = h3;
        s0 += h0 + h1; q0 += h0 * h0 + h1 * h1;
        s1 += h2 + h3; q1 += h2 * h2 + h3 * h3;
    }
#pragma unroll
    for (int o = 1; o <= 2; o <<= 1) {
        s0 += __shfl_xor_sync(0xffffffffu, s0, o);
        q0 += __shfl_xor_sync(0xffffffffu, q0, o);
        s1 += __shfl_xor_sync(0xffffffffu, s1, o);
        q1 += __shfl_xor_sync(0xffffffffu, q1, o);
    }
    const float inv_h = 1.f / 128.f;
    float mu0 = s0 * inv_h, var0 = q0 * inv_h - mu0 * mu0;
    float mu1 = s1 * inv_h, var1 = q1 * inv_h - mu1 * mu1;
    float rs0 = rsqrtf(var0 + LN_EPS);
    float rs1 = rsqrtf(var1 + LN_EPS);
    const float inv_sqrt2 = 0.70710678118654752f;

#pragma unroll
    for (int nt = 0; nt < 16; nt++) {
        int col = nt * 8 + tig * 2;
        float2 gg = *(const float2*)(gamma + col);
        float2 be = *(const float2*)(beta + col);
        if (r0 < N_NODES) {
            float2 xv = *(const float2*)(x + (size_t)r0 * HIDDEN + col);
            float hn0 = (c[nt][0] - mu0) * rs0 * gg.x + be.x;
            float hn1 = (c[nt][1] - mu0) * rs0 * gg.y + be.y;
            float g0 = 0.5f * hn0 * (1.f + erff(hn0 * inv_sqrt2));
            float g1 = 0.5f * hn1 * (1.f + erff(hn1 * inv_sqrt2));
            *(float2*)(out + (size_t)r0 * HIDDEN + col) = make_float2(xv.x + g0, xv.y + g1);
        }
        if (r1 < N_NODES) {
            float2 xv = *(const float2*)(x + (size_t)r1 * HIDDEN + col);
            float hn2 = (c[nt][2] - mu1) * rs1 * gg.x + be.x;
            float hn3 = (c[nt][3] - mu1) * rs1 * gg.y + be.y;
            float g2 = 0.5f * hn2 * (1.f + erff(hn2 * inv_sqrt2));
            float g3 = 0.5f * hn3 * (1.f + erff(hn3 * inv_sqrt2));
            *(float2*)(out + (size_t)r1 * HIDDEN + col) = make_float2(xv.x + g2, xv.y + g3);
        }
    }
}

extern "C" void kernel_launch(void* const* d_in, const int* in_sizes, int n_in,
                              void* d_out, int out_size) {
    const float* x     = (const float*)d_in[0];
    const int*   ei    = (const int*)d_in[1];
    const int*   et    = (const int*)d_in[2];
    const float* Wmsg  = (const float*)d_in[3];
    const float* bmsg  = (const float*)d_in[4];
    const float* Wupd  = (const float*)d_in[5];
    const float* bupd  = (const float*)d_in[6];
    const float* gamma = (const float*)d_in[7];
    const float* beta  = (const float*)d_in[8];
    float* out = (float*)d_out;

    const int PROJ_SM = (128 * APAD + 4 * 64 * BPAD) * 4;   // 206848 B
    const int UPD_SM  = (128 * APAD + 128 * BPAD) * 4;      // 137216 B
    cudaFuncSetAttribute(k_proj,   cudaFuncAttributeMaxDynamicSharedMemorySize, PROJ_SM);
    cudaFuncSetAttribute(k_update, cudaFuncAttributeMaxDynamicSharedMemorySize, UPD_SM);

    k_prep<<<256, 256>>>(Wmsg, Wupd);                       // zero + both W transposes
    k_hist<<<(N_EDGES + 255) / 256, 256>>>(ei, et);

    k_proj<<<(N_NODES + 127) / 128, 512, PROJ_SM>>>(x, bmsg);

    k_scan1<<<SCAN_BLOCKS, 1024>>>();
    k_scan2<<<1, 1>>>();
    k_fill<<<(N_EDGES + 255) / 256, 256>>>(ei, et);
    k_agg<<<(N_NODES + 7) / 8, 256>>>();

    k_update<<<(N_NODES + 127) / 128, 256, UPD_SM>>>(x, bupd, gamma, beta, out);
}

// round 14
// speedup vs baseline: 1.0308x; 1.0308x over previous
#include <cuda_runtime.h>
#include <math.h>
#include <stdint.h>

#define HIDDEN  128
#define N_NODES 50000
#define N_EDGES 600000
#define LN_EPS  1e-5f
#define APAD    132   // A-tile smem stride: conflict-free scalar frag loads
#define BPAD    136   // B-tile smem stride: conflict-free LDS.64 frag loads
#define SCAN_BLOCKS ((N_NODES + 1023) / 1024)   // 49

// Scratch (static device arrays: no allocation allowed)
__device__ uint32_t g_Ah[N_NODES * 3 * 64];    // per-node typed projections, bf16x2 packed
__device__ float g_agg[N_NODES * HIDDEN];      // B-term partial (proj epi) -> full agg
__device__ int   g_cnt[N_NODES * 4];           // per-node per-type edge counts
__device__ int   g_pos[N_NODES];               // CSR fill cursors
__device__ int   g_off[N_NODES + 1];           // CSR row offsets (block-local until + g_bsum)
__device__ int   g_csr[N_EDGES];               // packed (src<<2)|type
__device__ int   g_bsum[SCAN_BLOCKS];          // per-scan-block exclusive prefixes
__device__ float g_Wt[768 * 128];              // Wmsg^T [j][k], k perm-within-8
__device__ float g_Wut[128 * 256];             // Wupd^T [h][k], k perm-within-8

__device__ __constant__ int JT[12] = {0,1,2,3,4,5, 6,8,10, 7,9,11};

#define CPA16(sa, gp)      asm volatile("cp.async.cg.shared.global [%0],[%1],16;" :: "r"(sa), "l"(gp))
#define CPA16Z(sa, gp, sz) asm volatile("cp.async.cg.shared.global [%0],[%1],16,%2;" :: "r"(sa), "l"(gp), "r"(sz))
#define CPA_COMMIT()       asm volatile("cp.async.commit_group;")
#define CPA_WAIT(n)        asm volatile("cp.async.wait_group %0;" :: "n"(n))

#define MMA_TF32(c, a, b)                                                        \
    asm volatile(                                                                \
        "mma.sync.aligned.m16n8k8.row.col.f32.tf32.tf32.f32 "                    \
        "{%0,%1,%2,%3},{%4,%5,%6,%7},{%8,%9},{%0,%1,%2,%3};"                     \
        : "+f"((c)[0]), "+f"((c)[1]), "+f"((c)[2]), "+f"((c)[3])                 \
        : "r"((a)[0]), "r"((a)[1]), "r"((a)[2]), "r"((a)[3]),                    \
          "r"((b)[0]), "r"((b)[1]))

__device__ __forceinline__ int perm8(int k) {   // (k,k+4) pairs adjacent within 8-group
    return (k & ~7) | (((k & 3) << 1) | ((k >> 2) & 1));
}

__device__ __forceinline__ uint32_t pack_bf16(float lo, float hi) {
    uint32_t r;
    asm("cvt.rn.bf16x2.f32 %0, %1, %2;" : "=r"(r) : "f"(hi), "f"(lo));
    return r;
}

__device__ __forceinline__ float bflo(uint32_t u) { return __uint_as_float(u << 16); }
__device__ __forceinline__ float bfhi(uint32_t u) { return __uint_as_float(u & 0xffff0000u); }

// ---------------- fused prep: zero counters | transpose Wmsg | transpose Wupd ----------------
__global__ void k_prep(const float* __restrict__ Wmsg, const float* __restrict__ Wupd) {
    __shared__ float ts[32][33];
    const int b = blockIdx.x;
    const int tid = threadIdx.x;
    if (b < 128) {
        int i = b * 256 + tid;
        int stride = 128 * 256;
        for (int j = i; j < N_NODES * 4; j += stride) g_cnt[j] = 0;
        for (int j = i; j < N_NODES; j += stride) g_pos[j] = 0;
    } else if (b < 224) {
        int bb = b - 128;
        int mat = bb >> 4;
        int tile = bb & 15;
        int ti = tile >> 2, tj = tile & 3;
        int t_ = mat % 3, part = mat / 3;
        int rx = tid & 31, ry = tid >> 5;
#pragma unroll
        for (int p = 0; p < 4; p++) {
            int k = ti * 32 + ry + p * 8;
            ts[ry + p * 8][rx] = Wmsg[(t_ * 256 + part * 128 + k) * 128 + tj * 32 + rx];
        }
        __syncthreads();
#pragma unroll
        for (int p = 0; p < 4; p++) {
            int row = ry + p * 8;
            int kp = perm8(ti * 32 + rx);
            g_Wt[(part * 384 + t_ * 128 + tj * 32 + row) * 128 + kp] = ts[rx][row];
        }
    } else {
        int bb = b - 224;
        int ti = bb >> 2, tj = bb & 3;
        int rx = tid & 31, ry = tid >> 5;
#pragma unroll
        for (int p = 0; p < 4; p++)
            ts[ry + p * 8][rx] = Wupd[(ti * 32 + ry + p * 8) * 128 + tj * 32 + rx];
        __syncthreads();
#pragma unroll
        for (int p = 0; p < 4; p++) {
            int row = ry + p * 8;
            int kp = perm8(ti * 32 + rx);
            g_Wut[(tj * 32 + row) * 256 + kp] = ts[rx][row];
        }
    }
}

// ---------------- per-(dst,type) histogram ----------------
__global__ void k_hist(const int* __restrict__ ei, const int* __restrict__ et) {
    int e = blockIdx.x * blockDim.x + threadIdx.x;
    if (e >= N_EDGES) return;
    atomicAdd(&g_cnt[ei[N_EDGES + e] * 4 + et[e]], 1);
}

// ---------------- projection GEMM: A-in-regs, depth-2 double-buffered W (R10 structure) ------
__global__ void __launch_bounds__(512) k_proj(const float* __restrict__ x,
                                              const float* __restrict__ bmsg) {
    extern __shared__ float sm[];
    float* xs  = sm;                    // [128][APAD]
    float* wsb = sm + 128 * APAD;       // 2 x [64][BPAD]
    const int tid = threadIdx.x;
    const int n0 = blockIdx.x * 128;
    const uint32_t xs_b = (uint32_t)__cvta_generic_to_shared(xs);
    const uint32_t ws_b = (uint32_t)__cvta_generic_to_shared(wsb);

    for (int i = tid; i < 4096; i += 512) {
        int m = i >> 5, k4 = i & 31;
        int n = n0 + m;
        int sz = (n < N_NODES) ? 16 : 0;
        CPA16Z(xs_b + (m * APAD + k4 * 4) * 4, x + (size_t)n * 128 + k4 * 4, sz);
    }
    CPA_COMMIT();
    for (int i = tid; i < 2048; i += 512) {
        int r = i >> 5, k4 = i & 31;
        CPA16(ws_b + (r * BPAD + k4 * 4) * 4, g_Wt + r * 128 + k4 * 4);
    }
    CPA_COMMIT();

    const int w = tid >> 5, lane = tid & 31;
    const int gid = lane >> 2, tig = lane & 3;
    const int m0 = (w & 7) * 16;
    const int nw = (w >> 3) * 32;
    const int r0 = n0 + m0 + gid;

    CPA_WAIT(1);
    __syncthreads();
    uint32_t a[16][4];
    {
        const uint32_t* As = (const uint32_t*)xs;
#pragma unroll
        for (int ks = 0; ks < 16; ks++) {
            const uint32_t* ap = As + (m0 + gid) * APAD + ks * 8 + tig;
            a[ks][0] = ap[0];
            a[ks][1] = ap[8 * APAD];
            a[ks][2] = ap[4];
            a[ks][3] = ap[8 * APAD + 4];
        }
    }

    float accB[4][4];

    for (int idx = 0; idx < 12; idx++) {
        if (idx + 1 < 12) {
            uint32_t dst = ws_b + ((idx + 1) & 1) * 64 * BPAD * 4;
            const float* src = g_Wt + JT[idx + 1] * 64 * 128;
            for (int i = tid; i < 2048; i += 512) {
                int r = i >> 5, k4 = i & 31;
                CPA16(dst + (r * BPAD + k4 * 4) * 4, src + r * 128 + k4 * 4);
            }
            CPA_COMMIT();
            CPA_WAIT(1);
        } else {
            CPA_WAIT(0);
        }
        __syncthreads();

        const uint32_t* Ws = (const uint32_t*)(wsb + (idx & 1) * 64 * BPAD);

        float c[4][4];
#pragma unroll
        for (int nt = 0; nt < 4; nt++)
#pragma unroll
            for (int q = 0; q < 4; q++) c[nt][q] = 0.f;

#pragma unroll
        for (int ks = 0; ks < 16; ks++) {
#pragma unroll
            for (int nt = 0; nt < 4; nt++) {
                uint2 bv = *(const uint2*)(Ws + (nw + nt * 8 + gid) * BPAD + ks * 8 + tig * 2);
                uint32_t b[2] = {bv.x, bv.y};
                MMA_TF32(c[nt], a[ks], b);
            }
        }

        int j0 = JT[idx] * 64;
        if (j0 < 384) {
#pragma unroll
            for (int nt = 0; nt < 4; nt++) {
                int col = j0 + nw + nt * 8 + tig * 2;
                uint32_t p01 = pack_bf16(c[nt][0], c[nt][1]);
                uint32_t p23 = pack_bf16(c[nt][2], c[nt][3]);
                if (r0 < N_NODES)
                    g_Ah[(size_t)r0 * 192 + (col >> 1)] = p01;
                if (r0 + 8 < N_NODES)
                    g_Ah[(size_t)(r0 + 8) * 192 + (col >> 1)] = p23;
            }
        } else {
            int jj = j0 - 384;
            int t = jj >> 7;
            int h0 = jj & 127;
            float f0 = (r0 < N_NODES)     ? (float)g_cnt[r0 * 4 + t]       : 0.f;
            float f1 = (r0 + 8 < N_NODES) ? (float)g_cnt[(r0 + 8) * 4 + t] : 0.f;
#pragma unroll
            for (int nt = 0; nt < 4; nt++) {
                int hcol = h0 + nw + nt * 8 + tig * 2;
                float2 bm = *(const float2*)(bmsg + t * 128 + hcol);
                if (t == 0) { accB[nt][0] = 0.f; accB[nt][1] = 0.f; accB[nt][2] = 0.f; accB[nt][3] = 0.f; }
                accB[nt][0] += f0 * (c[nt][0] + bm.x);
                accB[nt][1] += f0 * (c[nt][1] + bm.y);
                accB[nt][2] += f1 * (c[nt][2] + bm.x);
                accB[nt][3] += f1 * (c[nt][3] + bm.y);
                if (t == 2) {
                    if (r0 < N_NODES)
                        *(float2*)(g_agg + (size_t)r0 * 128 + hcol) = make_float2(accB[nt][0], accB[nt][1]);
                    if (r0 + 8 < N_NODES)
                        *(float2*)(g_agg + (size_t)(r0 + 8) * 128 + hcol) = make_float2(accB[nt][2], accB[nt][3]);
                }
            }
        }
        __syncthreads();
    }
}

// ---------------- 2-phase parallel exclusive scan (block-local + block prefixes) -------------
__global__ void k_scan1() {
    __shared__ int wsum[32];
    const int tid = threadIdx.x, lane = tid & 31, wid = tid >> 5;
    int n = blockIdx.x * 1024 + tid;
    int v = 0;
    if (n < N_NODES) v = g_cnt[n * 4] + g_cnt[n * 4 + 1] + g_cnt[n * 4 + 2];
    int xv = v;
#pragma unroll
    for (int o = 1; o < 32; o <<= 1) {
        int y = __shfl_up_sync(0xffffffffu, xv, o);
        if (lane >= o) xv += y;
    }
    if (lane == 31) wsum[wid] = xv;
    __syncthreads();
    if (wid == 0) {
        int s = wsum[lane];
#pragma unroll
        for (int o = 1; o < 32; o <<= 1) {
            int y = __shfl_up_sync(0xffffffffu, s, o);
            if (lane >= o) s += y;
        }
        wsum[lane] = s;
    }
    __syncthreads();
    int excl = xv - v + (wid > 0 ? wsum[wid - 1] : 0);
    if (n < N_NODES) g_off[n] = excl;      // block-local exclusive prefix
    if (tid == 1023) g_bsum[blockIdx.x] = excl + v;
}

__global__ void k_scan2() {
    int run = 0;
    for (int b = 0; b < SCAN_BLOCKS; b++) {
        int t = g_bsum[b];
        g_bsum[b] = run;                   // exclusive block prefix
        run += t;
    }
}

// ---------------- CSR bucket fill (global offset = local + block prefix) ----------------
__global__ void k_fill(const int* __restrict__ ei, const int* __restrict__ et) {
    int e = blockIdx.x * blockDim.x + threadIdx.x;
    if (e >= N_EDGES) return;
    int dst = ei[N_EDGES + e];
    int p = atomicAdd(&g_pos[dst], 1);
    g_csr[g_off[dst] + g_bsum[dst >> 10] + p] = (ei[e] << 2) | et[e];
}

// ---------------- gather-aggregate (one warp per dst); 4 independent dependent-load lanes ----
__global__ void k_agg() {
    int n = (blockIdx.x * blockDim.x + threadIdx.x) >> 5;
    if (n >= N_NODES) return;
    int lane = threadIdx.x & 31;
    int beg = g_off[n] + g_bsum[n >> 10];
    int end = (n + 1 == N_NODES) ? N_EDGES : (g_off[n + 1] + g_bsum[(n + 1) >> 10]);
    int deg = end - beg;
    float4 a0 = ((const float4*)g_agg)[n * 32 + lane];   // cnt-weighted B + bias partial
    float4 a1 = make_float4(0.f, 0.f, 0.f, 0.f);
    float4 a2 = make_float4(0.f, 0.f, 0.f, 0.f);
    float4 a3 = make_float4(0.f, 0.f, 0.f, 0.f);
    const uint2* Ah = (const uint2*)g_Ah;

    int i = beg;
    for (; i + 4 <= end; i += 4) {
        int p0 = __ldg(&g_csr[i]);
        int p1 = __ldg(&g_csr[i + 1]);
        int p2 = __ldg(&g_csr[i + 2]);
        int p3 = __ldg(&g_csr[i + 3]);
        uint2 v0 = __ldg(Ah + (size_t)((p0 >> 2) * 3 + (p0 & 3)) * 32 + lane);
        uint2 v1 = __ldg(Ah + (size_t)((p1 >> 2) * 3 + (p1 & 3)) * 32 + lane);
        uint2 v2 = __ldg(Ah + (size_t)((p2 >> 2) * 3 + (p2 & 3)) * 32 + lane);
        uint2 v3 = __ldg(Ah + (size_t)((p3 >> 2) * 3 + (p3 & 3)) * 32 + lane);
        a0.x += bflo(v0.x); a0.y += bfhi(v0.x); a0.z += bflo(v0.y); a0.w += bfhi(v0.y);
        a1.x += bflo(v1.x); a1.y += bfhi(v1.x); a1.z += bflo(v1.y); a1.w += bfhi(v1.y);
        a2.x += bflo(v2.x); a2.y += bfhi(v2.x); a2.z += bflo(v2.y); a2.w += bfhi(v2.y);
        a3.x += bflo(v3.x); a3.y += bfhi(v3.x); a3.z += bflo(v3.y); a3.w += bfhi(v3.y);
    }
    for (; i < end; i++) {
        int p0 = __ldg(&g_csr[i]);
        uint2 v0 = __ldg(Ah + (size_t)((p0 >> 2) * 3 + (p0 & 3)) * 32 + lane);
        a0.x += bflo(v0.x); a0.y += bfhi(v0.x); a0.z += bflo(v0.y); a0.w += bfhi(v0.y);
    }
    a0.x += (a1.x + a2.x) + a3.x;
    a0.y += (a1.y + a2.y) + a3.y;
    a0.z += (a1.z + a2.z) + a3.z;
    a0.w += (a1.w + a2.w) + a3.w;
    float inv = 1.f / fmaxf((float)deg, 1.f);
    a0.x *= inv; a0.y *= inv; a0.z *= inv; a0.w *= inv;
    ((float4*)g_agg)[n * 32 + lane] = a0;
}

// ---------------- update GEMM (tf32, permuted W, cp.async) + fused LN/GELU/residual -----------
__global__ void __launch_bounds__(256) k_update(const float* __restrict__ x,
                                                const float* __restrict__ bupd,
                                                const float* __restrict__ gamma,
                                                const float* __restrict__ beta,
                                                float* __restrict__ out) {
    extern __shared__ float sm[];
    float* Is = sm;                 // [128][APAD]
    float* Ws = sm + 128 * APAD;    // [128][BPAD]
    const int tid = threadIdx.x;
    const int n0 = blockIdx.x * 128;
    const uint32_t is_b = (uint32_t)__cvta_generic_to_shared(Is);
    const uint32_t ws_b = (uint32_t)__cvta_generic_to_shared(Ws);
    const int w = tid >> 5, lane = tid & 31;
    const int gid = lane >> 2, tig = lane & 3;
    const int m0 = w * 16;

    float c[16][4];
#pragma unroll
    for (int nt = 0; nt < 16; nt++)
#pragma unroll
        for (int q = 0; q < 4; q++) c[nt][q] = 0.f;

    for (int kt = 0; kt < 2; kt++) {
        const float* src = kt ? g_agg : x;
        for (int i = tid; i < 4096; i += 256) {
            int m = i >> 5, k4 = i & 31;
            int n = n0 + m;
            int sz = (n < N_NODES) ? 16 : 0;
            CPA16Z(is_b + (m * APAD + k4 * 4) * 4, src + (size_t)n * 128 + k4 * 4, sz);
        }
        for (int i = tid; i < 4096; i += 256) {
            int h = i >> 5, k4 = i & 31;
            CPA16(ws_b + (h * BPAD + k4 * 4) * 4, g_Wut + h * 256 + kt * 128 + k4 * 4);
        }
        CPA_COMMIT();
        CPA_WAIT(0);
        __syncthreads();

        const uint32_t* IsU = (const uint32_t*)Is;
        const uint32_t* WsU = (const uint32_t*)Ws;
#pragma unroll
        for (int ks = 0; ks < 16; ks++) {
            int kb = ks * 8;
            uint32_t a[4];
            const uint32_t* ap = IsU + (m0 + gid) * APAD + kb + tig;
            a[0] = ap[0];
            a[1] = ap[8 * APAD];
            a[2] = ap[4];
            a[3] = ap[8 * APAD + 4];
#pragma unroll
            for (int nt = 0; nt < 16; nt++) {
                uint2 bv = *(const uint2*)(WsU + (nt * 8 + gid) * BPAD + kb + tig * 2);
                uint32_t b[2] = {bv.x, bv.y};
                MMA_TF32(c[nt], a, b);
            }
        }
        __syncthreads();
    }

    const int r0 = n0 + m0 + gid;
    const int r1 = r0 + 8;
    float s0 = 0.f, q0 = 0.f, s1 = 0.f, q1 = 0.f;
#pragma unroll
    for (int nt = 0; nt < 16; nt++) {
        int col = nt * 8 + tig * 2;
        float2 bb = *(const float2*)(bupd + col);
        float h0 = c[nt][0] + bb.x, h1 = c[nt][1] + bb.y;
        float h2 = c[nt][2] + bb.x, h3 = c[nt][3] + bb.y;
        c[nt][0] = h0; c[nt][1] = h1; c[nt][2] = h2; c[nt][3] = h3;
        s0 += h0 + h1; q0 += h0 * h0 + h1 * h1;
        s1 += h2 + h3; q1 += h2 * h2 + h3 * h3;
    }
#pragma unroll
    for (int o = 1; o <= 2; o <<= 1) {
        s0 += __shfl_xor_sync(0xffffffffu, s0, o);
        q0 += __shfl_xor_sync(0xffffffffu, q0, o);
        s1 += __shfl_xor_sync(0xffffffffu, s1, o);
        q1 += __shfl_xor_sync(0xffffffffu, q1, o);
    }
    const float inv_h = 1.f / 128.f;
    float mu0 = s0 * inv_h, var0 = q0 * inv_h - mu0 * mu0;
    float mu1 = s1 * inv_h, var1 = q1 * inv_h - mu1 * mu1;
    float rs0 = rsqrtf(var0 + LN_EPS);
    float rs1 = rsqrtf(var1 + LN_EPS);
    const float inv_sqrt2 = 0.70710678118654752f;

#pragma unroll
    for (int nt = 0; nt < 16; nt++) {
        int col = nt * 8 + tig * 2;
        float2 gg = *(const float2*)(gamma + col);
        float2 be = *(const float2*)(beta + col);
        if (r0 < N_NODES) {
            float2 xv = *(const float2*)(x + (size_t)r0 * HIDDEN + col);
            float hn0 = (c[nt][0] - mu0) * rs0 * gg.x + be.x;
            float hn1 = (c[nt][1] - mu0) * rs0 * gg.y + be.y;
            float g0 = 0.5f * hn0 * (1.f + erff(hn0 * inv_sqrt2));
            float g1 = 0.5f * hn1 * (1.f + erff(hn1 * inv_sqrt2));
            *(float2*)(out + (size_t)r0 * HIDDEN + col) = make_float2(xv.x + g0, xv.y + g1);
        }
        if (r1 < N_NODES) {
            float2 xv = *(const float2*)(x + (size_t)r1 * HIDDEN + col);
            float hn2 = (c[nt][2] - mu1) * rs1 * gg.x + be.x;
            float hn3 = (c[nt][3] - mu1) * rs1 * gg.y + be.y;
            float g2 = 0.5f * hn2 * (1.f + erff(hn2 * inv_sqrt2));
            float g3 = 0.5f * hn3 * (1.f + erff(hn3 * inv_sqrt2));
            *(float2*)(out + (size_t)r1 * HIDDEN + col) = make_float2(xv.x + g2, xv.y + g3);
        }
    }
}

extern "C" void kernel_launch(void* const* d_in, const int* in_sizes, int n_in,
                              void* d_out, int out_size) {
    const float* x     = (const float*)d_in[0];
    const int*   ei    = (const int*)d_in[1];
    const int*   et    = (const int*)d_in[2];
    const float* Wmsg  = (const float*)d_in[3];
    const float* bmsg  = (const float*)d_in[4];
    const float* Wupd  = (const float*)d_in[5];
    const float* bupd  = (const float*)d_in[6];
    const float* gamma = (const float*)d_in[7];
    const float* beta  = (const float*)d_in[8];
    float* out = (float*)d_out;

    const int PROJ_SM = (128 * APAD + 2 * 64 * BPAD) * 4;   // 137216 B
    const int UPD_SM  = (128 * APAD + 128 * BPAD) * 4;      // 137216 B
    cudaFuncSetAttribute(k_proj,   cudaFuncAttributeMaxDynamicSharedMemorySize, PROJ_SM);
    cudaFuncSetAttribute(k_update, cudaFuncAttributeMaxDynamicSharedMemorySize, UPD_SM);

    k_prep<<<256, 256>>>(Wmsg, Wupd);                       // zero + both W transposes
    k_hist<<<(N_EDGES + 255) / 256, 256>>>(ei, et);

    k_proj<<<(N_NODES + 127) / 128, 512, PROJ_SM>>>(x, bmsg);

    k_scan1<<<SCAN_BLOCKS, 1024>>>();
    k_scan2<<<1, 1>>>();
    k_fill<<<(N_EDGES + 255) / 256, 256>>>(ei, et);
    k_agg<<<(N_NODES + 7) / 8, 256>>>();

    k_update<<<(N_NODES + 127) / 128, 256, UPD_SM>>>(x, bupd, gamma, beta, out);
}

// round 15
// speedup vs baseline: 1.1269x; 1.0931x over previous
#include <cuda_runtime.h>
#include <math.h>
#include <stdint.h>

#define HIDDEN  128
#define N_NODES 50000
#define N_EDGES 600000
#define LN_EPS  1e-5f
#define APAD    132   // A-tile smem stride: conflict-free scalar frag loads
#define BPAD    136   // B-tile smem stride: conflict-free LDS.64 frag loads
#define SCAN_BLOCKS ((N_NODES + 1023) / 1024)   // 49

// Scratch (static device arrays: no allocation allowed)
__device__ uint32_t g_Ah[N_NODES * 3 * 64];    // per-node typed projections, bf16x2 packed
__device__ float g_agg[N_NODES * HIDDEN];      // B-term partial (proj epi) -> full agg
__device__ int   g_cnt[N_NODES * 4];           // per-node per-type edge counts
__device__ int   g_pos[N_NODES];               // CSR fill cursors
__device__ int   g_off[N_NODES + 1];           // CSR row offsets (block-local until + g_bsum)
__device__ int   g_csr[N_EDGES];               // packed (src<<2)|type
__device__ int   g_bsum[SCAN_BLOCKS];          // per-scan-block exclusive prefixes
__device__ float g_Wt[768 * 128];              // Wmsg^T [j][k], k perm-within-8
__device__ float g_Wut[128 * 256];             // Wupd^T [h][k], k perm-within-8

__device__ __constant__ int JT[12] = {0,1,2,3,4,5, 6,8,10, 7,9,11};

#define CPA16(sa, gp)      asm volatile("cp.async.cg.shared.global [%0],[%1],16;" :: "r"(sa), "l"(gp))
#define CPA16Z(sa, gp, sz) asm volatile("cp.async.cg.shared.global [%0],[%1],16,%2;" :: "r"(sa), "l"(gp), "r"(sz))
#define CPA_COMMIT()       asm volatile("cp.async.commit_group;")
#define CPA_WAIT(n)        asm volatile("cp.async.wait_group %0;" :: "n"(n))

#define MMA_TF32(c, a, b)                                                        \
    asm volatile(                                                                \
        "mma.sync.aligned.m16n8k8.row.col.f32.tf32.tf32.f32 "                    \
        "{%0,%1,%2,%3},{%4,%5,%6,%7},{%8,%9},{%0,%1,%2,%3};"                     \
        : "+f"((c)[0]), "+f"((c)[1]), "+f"((c)[2]), "+f"((c)[3])                 \
        : "r"((a)[0]), "r"((a)[1]), "r"((a)[2]), "r"((a)[3]),                    \
          "r"((b)[0]), "r"((b)[1]))

__device__ __forceinline__ int perm8(int k) {   // (k,k+4) pairs adjacent within 8-group
    return (k & ~7) | (((k & 3) << 1) | ((k >> 2) & 1));
}

__device__ __forceinline__ uint32_t pack_bf16(float lo, float hi) {
    uint32_t r;
    asm("cvt.rn.bf16x2.f32 %0, %1, %2;" : "=r"(r) : "f"(hi), "f"(lo));
    return r;
}

__device__ __forceinline__ float bflo(uint32_t u) { return __uint_as_float(u << 16); }
__device__ __forceinline__ float bfhi(uint32_t u) { return __uint_as_float(u & 0xffff0000u); }

// ---------------- fused prep: zero counters | transpose Wmsg | transpose Wupd ----------------
__global__ void k_prep(const float* __restrict__ Wmsg, const float* __restrict__ Wupd) {
    __shared__ float ts[32][33];
    const int b = blockIdx.x;
    const int tid = threadIdx.x;
    if (b < 128) {
        int i = b * 256 + tid;
        int stride = 128 * 256;
        for (int j = i; j < N_NODES * 4; j += stride) g_cnt[j] = 0;
        for (int j = i; j < N_NODES; j += stride) g_pos[j] = 0;
    } else if (b < 224) {
        int bb = b - 128;
        int mat = bb >> 4;
        int tile = bb & 15;
        int ti = tile >> 2, tj = tile & 3;
        int t_ = mat % 3, part = mat / 3;
        int rx = tid & 31, ry = tid >> 5;
#pragma unroll
        for (int p = 0; p < 4; p++) {
            int k = ti * 32 + ry + p * 8;
            ts[ry + p * 8][rx] = Wmsg[(t_ * 256 + part * 128 + k) * 128 + tj * 32 + rx];
        }
        __syncthreads();
#pragma unroll
        for (int p = 0; p < 4; p++) {
            int row = ry + p * 8;
            int kp = perm8(ti * 32 + rx);
            g_Wt[(part * 384 + t_ * 128 + tj * 32 + row) * 128 + kp] = ts[rx][row];
        }
    } else {
        int bb = b - 224;
        int ti = bb >> 2, tj = bb & 3;
        int rx = tid & 31, ry = tid >> 5;
#pragma unroll
        for (int p = 0; p < 4; p++)
            ts[ry + p * 8][rx] = Wupd[(ti * 32 + ry + p * 8) * 128 + tj * 32 + rx];
        __syncthreads();
#pragma unroll
        for (int p = 0; p < 4; p++) {
            int row = ry + p * 8;
            int kp = perm8(ti * 32 + rx);
            g_Wut[(tj * 32 + row) * 256 + kp] = ts[rx][row];
        }
    }
}

// ---------------- per-(dst,type) histogram ----------------
__global__ void k_hist(const int* __restrict__ ei, const int* __restrict__ et) {
    int e = blockIdx.x * blockDim.x + threadIdx.x;
    if (e >= N_EDGES) return;
    atomicAdd(&g_cnt[ei[N_EDGES + e] * 4 + et[e]], 1);
}

// ---------------- projection GEMM: A-in-regs, depth-2 double-buffered W ----------------------
__global__ void __launch_bounds__(512) k_proj(const float* __restrict__ x,
                                              const float* __restrict__ bmsg) {
    extern __shared__ float sm[];
    float* xs  = sm;                    // [128][APAD]
    float* wsb = sm + 128 * APAD;       // 2 x [64][BPAD]
    const int tid = threadIdx.x;
    const int n0 = blockIdx.x * 128;
    const uint32_t xs_b = (uint32_t)__cvta_generic_to_shared(xs);
    const uint32_t ws_b = (uint32_t)__cvta_generic_to_shared(wsb);

    for (int i = tid; i < 4096; i += 512) {
        int m = i >> 5, k4 = i & 31;
        int n = n0 + m;
        int sz = (n < N_NODES) ? 16 : 0;
        CPA16Z(xs_b + (m * APAD + k4 * 4) * 4, x + (size_t)n * 128 + k4 * 4, sz);
    }
    CPA_COMMIT();
    for (int i = tid; i < 2048; i += 512) {
        int r = i >> 5, k4 = i & 31;
        CPA16(ws_b + (r * BPAD + k4 * 4) * 4, g_Wt + r * 128 + k4 * 4);
    }
    CPA_COMMIT();

    const int w = tid >> 5, lane = tid & 31;
    const int gid = lane >> 2, tig = lane & 3;
    const int m0 = (w & 7) * 16;
    const int nw = (w >> 3) * 32;
    const int r0 = n0 + m0 + gid;

    CPA_WAIT(1);
    __syncthreads();
    uint32_t a[16][4];
    {
        const uint32_t* As = (const uint32_t*)xs;
#pragma unroll
        for (int ks = 0; ks < 16; ks++) {
            const uint32_t* ap = As + (m0 + gid) * APAD + ks * 8 + tig;
            a[ks][0] = ap[0];
            a[ks][1] = ap[8 * APAD];
            a[ks][2] = ap[4];
            a[ks][3] = ap[8 * APAD + 4];
        }
    }

    float accB[4][4];

    for (int idx = 0; idx < 12; idx++) {
        if (idx + 1 < 12) {
            uint32_t dst = ws_b + ((idx + 1) & 1) * 64 * BPAD * 4;
            const float* src = g_Wt + JT[idx + 1] * 64 * 128;
            for (int i = tid; i < 2048; i += 512) {
                int r = i >> 5, k4 = i & 31;
                CPA16(dst + (r * BPAD + k4 * 4) * 4, src + r * 128 + k4 * 4);
            }
            CPA_COMMIT();
            CPA_WAIT(1);
        } else {
            CPA_WAIT(0);
        }
        __syncthreads();

        const uint32_t* Ws = (const uint32_t*)(wsb + (idx & 1) * 64 * BPAD);

        float c[4][4];
#pragma unroll
        for (int nt = 0; nt < 4; nt++)
#pragma unroll
            for (int q = 0; q < 4; q++) c[nt][q] = 0.f;

#pragma unroll
        for (int ks = 0; ks < 16; ks++) {
#pragma unroll
            for (int nt = 0; nt < 4; nt++) {
                uint2 bv = *(const uint2*)(Ws + (nw + nt * 8 + gid) * BPAD + ks * 8 + tig * 2);
                uint32_t b[2] = {bv.x, bv.y};
                MMA_TF32(c[nt], a[ks], b);
            }
        }

        int j0 = JT[idx] * 64;
        if (j0 < 384) {
#pragma unroll
            for (int nt = 0; nt < 4; nt++) {
                int col = j0 + nw + nt * 8 + tig * 2;
                uint32_t p01 = pack_bf16(c[nt][0], c[nt][1]);
                uint32_t p23 = pack_bf16(c[nt][2], c[nt][3]);
                if (r0 < N_NODES)
                    g_Ah[(size_t)r0 * 192 + (col >> 1)] = p01;
                if (r0 + 8 < N_NODES)
                    g_Ah[(size_t)(r0 + 8) * 192 + (col >> 1)] = p23;
            }
        } else {
            int jj = j0 - 384;
            int t = jj >> 7;
            int h0 = jj & 127;
            float f0 = (r0 < N_NODES)     ? (float)g_cnt[r0 * 4 + t]       : 0.f;
            float f1 = (r0 + 8 < N_NODES) ? (float)g_cnt[(r0 + 8) * 4 + t] : 0.f;
#pragma unroll
            for (int nt = 0; nt < 4; nt++) {
                int hcol = h0 + nw + nt * 8 + tig * 2;
                float2 bm = *(const float2*)(bmsg + t * 128 + hcol);
                if (t == 0) { accB[nt][0] = 0.f; accB[nt][1] = 0.f; accB[nt][2] = 0.f; accB[nt][3] = 0.f; }
                accB[nt][0] += f0 * (c[nt][0] + bm.x);
                accB[nt][1] += f0 * (c[nt][1] + bm.y);
                accB[nt][2] += f1 * (c[nt][2] + bm.x);
                accB[nt][3] += f1 * (c[nt][3] + bm.y);
                if (t == 2) {
                    if (r0 < N_NODES)
                        *(float2*)(g_agg + (size_t)r0 * 128 + hcol) = make_float2(accB[nt][0], accB[nt][1]);
                    if (r0 + 8 < N_NODES)
                        *(float2*)(g_agg + (size_t)(r0 + 8) * 128 + hcol) = make_float2(accB[nt][2], accB[nt][3]);
                }
            }
        }
        __syncthreads();
    }
}

// ---------------- 2-phase parallel exclusive scan (block-local + block prefixes) -------------
__global__ void k_scan1() {
    __shared__ int wsum[32];
    const int tid = threadIdx.x, lane = tid & 31, wid = tid >> 5;
    int n = blockIdx.x * 1024 + tid;
    int v = 0;
    if (n < N_NODES) v = g_cnt[n * 4] + g_cnt[n * 4 + 1] + g_cnt[n * 4 + 2];
    int xv = v;
#pragma unroll
    for (int o = 1; o < 32; o <<= 1) {
        int y = __shfl_up_sync(0xffffffffu, xv, o);
        if (lane >= o) xv += y;
    }
    if (lane == 31) wsum[wid] = xv;
    __syncthreads();
    if (wid == 0) {
        int s = wsum[lane];
#pragma unroll
        for (int o = 1; o < 32; o <<= 1) {
            int y = __shfl_up_sync(0xffffffffu, s, o);
            if (lane >= o) s += y;
        }
        wsum[lane] = s;
    }
    __syncthreads();
    int excl = xv - v + (wid > 0 ? wsum[wid - 1] : 0);
    if (n < N_NODES) g_off[n] = excl;      // block-local exclusive prefix
    if (tid == 1023) g_bsum[blockIdx.x] = excl + v;
}

__global__ void k_scan2() {
    int run = 0;
    for (int b = 0; b < SCAN_BLOCKS; b++) {
        int t = g_bsum[b];
        g_bsum[b] = run;                   // exclusive block prefix
        run += t;
    }
}

// ---------------- CSR bucket fill (global offset = local + block prefix) ----------------
__global__ void k_fill(const int* __restrict__ ei, const int* __restrict__ et) {
    int e = blockIdx.x * blockDim.x + threadIdx.x;
    if (e >= N_EDGES) return;
    int dst = ei[N_EDGES + e];
    int p = atomicAdd(&g_pos[dst], 1);
    g_csr[g_off[dst] + g_bsum[dst >> 10] + p] = (ei[e] << 2) | et[e];
}

// ---------------- gather-aggregate (one warp per dst); 4 independent gathers in flight -------
__global__ void k_agg() {
    int n = (blockIdx.x * blockDim.x + threadIdx.x) >> 5;
    if (n >= N_NODES) return;
    int lane = threadIdx.x & 31;
    int beg = g_off[n] + g_bsum[n >> 10];
    int end = (n + 1 == N_NODES) ? N_EDGES : (g_off[n + 1] + g_bsum[(n + 1) >> 10]);
    int deg = end - beg;
    float4 a0 = ((const float4*)g_agg)[n * 32 + lane];   // cnt-weighted B + bias partial
    float4 a1 = make_float4(0.f, 0.f, 0.f, 0.f);
    float4 a2 = make_float4(0.f, 0.f, 0.f, 0.f);
    float4 a3 = make_float4(0.f, 0.f, 0.f, 0.f);
    const uint2* Ah = (const uint2*)g_Ah;

    int i = beg;
    for (; i + 4 <= end; i += 4) {
        int p0 = __ldg(&g_csr[i]);
        int p1 = __ldg(&g_csr[i + 1]);
        int p2 = __ldg(&g_csr[i + 2]);
        int p3 = __ldg(&g_csr[i + 3]);
        uint2 v0 = __ldg(Ah + (size_t)((p0 >> 2) * 3 + (p0 & 3)) * 32 + lane);
        uint2 v1 = __ldg(Ah + (size_t)((p1 >> 2) * 3 + (p1 & 3)) * 32 + lane);
        uint2 v2 = __ldg(Ah + (size_t)((p2 >> 2) * 3 + (p2 & 3)) * 32 + lane);
        uint2 v3 = __ldg(Ah + (size_t)((p3 >> 2) * 3 + (p3 & 3)) * 32 + lane);
        a0.x += bflo(v0.x); a0.y += bfhi(v0.x); a0.z += bflo(v0.y); a0.w += bfhi(v0.y);
        a1.x += bflo(v1.x); a1.y += bfhi(v1.x); a1.z += bflo(v1.y); a1.w += bfhi(v1.y);
        a2.x += bflo(v2.x); a2.y += bfhi(v2.x); a2.z += bflo(v2.y); a2.w += bfhi(v2.y);
        a3.x += bflo(v3.x); a3.y += bfhi(v3.x); a3.z += bflo(v3.y); a3.w += bfhi(v3.y);
    }
    for (; i < end; i++) {
        int p0 = __ldg(&g_csr[i]);
        uint2 v0 = __ldg(Ah + (size_t)((p0 >> 2) * 3 + (p0 & 3)) * 32 + lane);
        a0.x += bflo(v0.x); a0.y += bfhi(v0.x); a0.z += bflo(v0.y); a0.w += bfhi(v0.y);
    }
    a0.x += (a1.x + a2.x) + a3.x;
    a0.y += (a1.y + a2.y) + a3.y;
    a0.z += (a1.z + a2.z) + a3.z;
    a0.w += (a1.w + a2.w) + a3.w;
    float inv = 1.f / fmaxf((float)deg, 1.f);
    a0.x *= inv; a0.y *= inv; a0.z *= inv; a0.w *= inv;
    ((float4*)g_agg)[n * 32 + lane] = a0;
}

// ---------------- update GEMM (tf32, permuted W, cp.async) + fused LN/GELU/residual -----------
__global__ void __launch_bounds__(256) k_update(const float* __restrict__ x,
                                                const float* __restrict__ bupd,
                                                const float* __restrict__ gamma,
                                                const float* __restrict__ beta,
                                                float* __restrict__ out) {
    extern __shared__ float sm[];
    float* Is = sm;                 // [128][APAD]
    float* Ws = sm + 128 * APAD;    // [128][BPAD]
    const int tid = threadIdx.x;
    const int n0 = blockIdx.x * 128;
    const uint32_t is_b = (uint32_t)__cvta_generic_to_shared(Is);
    const uint32_t ws_b = (uint32_t)__cvta_generic_to_shared(Ws);
    const int w = tid >> 5, lane = tid & 31;
    const int gid = lane >> 2, tig = lane & 3;
    const int m0 = w * 16;

    float c[16][4];
#pragma unroll
    for (int nt = 0; nt < 16; nt++)
#pragma unroll
        for (int q = 0; q < 4; q++) c[nt][q] = 0.f;

    for (int kt = 0; kt < 2; kt++) {
        const float* src = kt ? g_agg : x;
        for (int i = tid; i < 4096; i += 256) {
            int m = i >> 5, k4 = i & 31;
            int n = n0 + m;
            int sz = (n < N_NODES) ? 16 : 0;
            CPA16Z(is_b + (m * APAD + k4 * 4) * 4, src + (size_t)n * 128 + k4 * 4, sz);
        }
        for (int i = tid; i < 4096; i += 256) {
            int h = i >> 5, k4 = i & 31;
            CPA16(ws_b + (h * BPAD + k4 * 4) * 4, g_Wut + h * 256 + kt * 128 + k4 * 4);
        }
        CPA_COMMIT();
        CPA_WAIT(0);
        __syncthreads();

        const uint32_t* IsU = (const uint32_t*)Is;
        const uint32_t* WsU = (const uint32_t*)Ws;
#pragma unroll
        for (int ks = 0; ks < 16; ks++) {
            int kb = ks * 8;
            uint32_t a[4];
            const uint32_t* ap = IsU + (m0 + gid) * APAD + kb + tig;
            a[0] = ap[0];
            a[1] = ap[8 * APAD];
            a[2] = ap[4];
            a[3] = ap[8 * APAD + 4];
#pragma unroll
            for (int nt = 0; nt < 16; nt++) {
                uint2 bv = *(const uint2*)(WsU + (nt * 8 + gid) * BPAD + kb + tig * 2);
                uint32_t b[2] = {bv.x, bv.y};
                MMA_TF32(c[nt], a, b);
            }
        }
        __syncthreads();
    }

    const int r0 = n0 + m0 + gid;
    const int r1 = r0 + 8;
    float s0 = 0.f, q0 = 0.f, s1 = 0.f, q1 = 0.f;
#pragma unroll
    for (int nt = 0; nt < 16; nt++) {
        int col = nt * 8 + tig * 2;
        float2 bb = *(const float2*)(bupd + col);
        float h0 = c[nt][0] + bb.x, h1 = c[nt][1] + bb.y;
        float h2 = c[nt][2] + bb.x, h3 = c[nt][3] + bb.y;
        c[nt][0] = h0; c[nt][1] = h1; c[nt][2] = h2; c[nt][3] = h3;
        s0 += h0 + h1; q0 += h0 * h0 + h1 * h1;
        s1 += h2 + h3; q1 += h2 * h2 + h3 * h3;
    }
#pragma unroll
    for (int o = 1; o <= 2; o <<= 1) {
        s0 += __shfl_xor_sync(0xffffffffu, s0, o);
        q0 += __shfl_xor_sync(0xffffffffu, q0, o);
        s1 += __shfl_xor_sync(0xffffffffu, s1, o);
        q1 += __shfl_xor_sync(0xffffffffu, q1, o);
    }
    const float inv_h = 1.f / 128.f;
    float mu0 = s0 * inv_h, var0 = q0 * inv_h - mu0 * mu0;
    float mu1 = s1 * inv_h, var1 = q1 * inv_h - mu1 * mu1;
    float rs0 = rsqrtf(var0 + LN_EPS);
    float rs1 = rsqrtf(var1 + LN_EPS);
    const float inv_sqrt2 = 0.70710678118654752f;

#pragma unroll
    for (int nt = 0; nt < 16; nt++) {
        int col = nt * 8 + tig * 2;
        float2 gg = *(const float2*)(gamma + col);
        float2 be = *(const float2*)(beta + col);
        if (r0 < N_NODES) {
            float2 xv = *(const float2*)(x + (size_t)r0 * HIDDEN + col);
            float hn0 = (c[nt][0] - mu0) * rs0 * gg.x + be.x;
            float hn1 = (c[nt][1] - mu0) * rs0 * gg.y + be.y;
            float g0 = 0.5f * hn0 * (1.f + erff(hn0 * inv_sqrt2));
            float g1 = 0.5f * hn1 * (1.f + erff(hn1 * inv_sqrt2));
            *(float2*)(out + (size_t)r0 * HIDDEN + col) = make_float2(xv.x + g0, xv.y + g1);
        }
        if (r1 < N_NODES) {
            float2 xv = *(const float2*)(x + (size_t)r1 * HIDDEN + col);
            float hn2 = (c[nt][2] - mu1) * rs1 * gg.x + be.x;
            float hn3 = (c[nt][3] - mu1) * rs1 * gg.y + be.y;
            float g2 = 0.5f * hn2 * (1.f + erff(hn2 * inv_sqrt2));
            float g3 = 0.5f * hn3 * (1.f + erff(hn3 * inv_sqrt2));
            *(float2*)(out + (size_t)r1 * HIDDEN + col) = make_float2(xv.x + g2, xv.y + g3);
        }
    }
}

extern "C" void kernel_launch(void* const* d_in, const int* in_sizes, int n_in,
                              void* d_out, int out_size) {
    const float* x     = (const float*)d_in[0];
    const int*   ei    = (const int*)d_in[1];
    const int*   et    = (const int*)d_in[2];
    const float* Wmsg  = (const float*)d_in[3];
    const float* bmsg  = (const float*)d_in[4];
    const float* Wupd  = (const float*)d_in[5];
    const float* bupd  = (const float*)d_in[6];
    const float* gamma = (const float*)d_in[7];
    const float* beta  = (const float*)d_in[8];
    float* out = (float*)d_out;

    // One-time side stream + events (host objects, not device memory; created outside capture
    // on the first (correctness) call, reused on every call -> identical work each call).
    static cudaStream_t s2 = nullptr;
    static cudaEvent_t ev_fork = nullptr, ev_join = nullptr;
    if (s2 == nullptr) {
        cudaStreamCreateWithFlags(&s2, cudaStreamNonBlocking);
        cudaEventCreateWithFlags(&ev_fork, cudaEventDisableTiming);
        cudaEventCreateWithFlags(&ev_join, cudaEventDisableTiming);
    }

    const int PROJ_SM = (128 * APAD + 2 * 64 * BPAD) * 4;   // 137216 B
    const int UPD_SM  = (128 * APAD + 128 * BPAD) * 4;      // 137216 B
    cudaFuncSetAttribute(k_proj,   cudaFuncAttributeMaxDynamicSharedMemorySize, PROJ_SM);
    cudaFuncSetAttribute(k_update, cudaFuncAttributeMaxDynamicSharedMemorySize, UPD_SM);

    k_prep<<<256, 256>>>(Wmsg, Wupd);                       // zero + both W transposes
    k_hist<<<(N_EDGES + 255) / 256, 256>>>(ei, et);

    // Fork: CSR build (scan1 -> scan2 -> fill) on s2, concurrent with k_proj on main stream.
    cudaEventRecord(ev_fork, 0);
    cudaStreamWaitEvent(s2, ev_fork, 0);
    k_scan1<<<SCAN_BLOCKS, 1024, 0, s2>>>();
    k_scan2<<<1, 1, 0, s2>>>();
    k_fill<<<(N_EDGES + 255) / 256, 256, 0, s2>>>(ei, et);
    cudaEventRecord(ev_join, s2);

    k_proj<<<(N_NODES + 127) / 128, 512, PROJ_SM>>>(x, bmsg);

    // Join: agg needs both proj (g_Ah, g_agg partial) and fill (g_csr).
    cudaStreamWaitEvent(0, ev_join, 0);
    k_agg<<<(N_NODES + 7) / 8, 256>>>();

    k_update<<<(N_NODES + 127) / 128, 256, UPD_SM>>>(x, bupd, gamma, beta, out);
}

// round 17
// speedup vs baseline: 1.1451x; 1.0162x over previous
#include <cuda_runtime.h>
#include <math.h>
#include <stdint.h>

#define HIDDEN  128
#define N_NODES 50000
#define N_EDGES 600000
#define LN_EPS  1e-5f
#define APAD    132   // A-tile smem stride: conflict-free scalar frag loads
#define BPAD    136   // B-tile smem stride: conflict-free LDS.64 frag loads
#define SCAN_BLOCKS ((N_NODES + 1023) / 1024)   // 49

// Scratch (static device arrays: no allocation allowed)
__device__ uint32_t g_Ah[N_NODES * 3 * 64];    // per-node typed projections, bf16x2 packed
__device__ float g_agg[N_NODES * HIDDEN];      // B-term partial (proj epi) -> full agg
__device__ int   g_cnt[N_NODES * 4];           // per-node per-type edge counts
__device__ int   g_pos[N_NODES];               // CSR fill cursors
__device__ int   g_off[N_NODES + 1];           // CSR row offsets (block-local until + g_bsum)
__device__ int   g_csr[N_EDGES];               // packed (src<<2)|type
__device__ int   g_bsum[SCAN_BLOCKS];          // per-scan-block exclusive prefixes
__device__ float g_Wt[768 * 128];              // Wmsg^T [j][k], k perm-within-8
__device__ float g_Wut[128 * 256];             // Wupd^T [h][k], k perm-within-8

__device__ __constant__ int JT[12] = {0,1,2,3,4,5, 6,8,10, 7,9,11};

#define CPA16(sa, gp)      asm volatile("cp.async.cg.shared.global [%0],[%1],16;" :: "r"(sa), "l"(gp))
#define CPA16Z(sa, gp, sz) asm volatile("cp.async.cg.shared.global [%0],[%1],16,%2;" :: "r"(sa), "l"(gp), "r"(sz))
#define CPA_COMMIT()       asm volatile("cp.async.commit_group;")
#define CPA_WAIT(n)        asm volatile("cp.async.wait_group %0;" :: "n"(n))

#define MMA_TF32(c, a, b)                                                        \
    asm volatile(                                                                \
        "mma.sync.aligned.m16n8k8.row.col.f32.tf32.tf32.f32 "                    \
        "{%0,%1,%2,%3},{%4,%5,%6,%7},{%8,%9},{%0,%1,%2,%3};"                     \
        : "+f"((c)[0]), "+f"((c)[1]), "+f"((c)[2]), "+f"((c)[3])                 \
        : "r"((a)[0]), "r"((a)[1]), "r"((a)[2]), "r"((a)[3]),                    \
          "r"((b)[0]), "r"((b)[1]))

__device__ __forceinline__ int perm8(int k) {   // (k,k+4) pairs adjacent within 8-group
    return (k & ~7) | (((k & 3) << 1) | ((k >> 2) & 1));
}

__device__ __forceinline__ uint32_t pack_bf16(float lo, float hi) {
    uint32_t r;
    asm("cvt.rn.bf16x2.f32 %0, %1, %2;" : "=r"(r) : "f"(hi), "f"(lo));
    return r;
}

__device__ __forceinline__ float bflo(uint32_t u) { return __uint_as_float(u << 16); }
__device__ __forceinline__ float bfhi(uint32_t u) { return __uint_as_float(u & 0xffff0000u); }

// ---------------- zero counters (main stream, before hist) ----------------
__global__ void k_zero() {
    int i = blockIdx.x * blockDim.x + threadIdx.x;
    int stride = gridDim.x * blockDim.x;
    for (int j = i; j < N_NODES * 4; j += stride) g_cnt[j] = 0;
    for (int j = i; j < N_NODES; j += stride) g_pos[j] = 0;
}

// ---------------- weight transposes (side stream, overlapped with zero+hist) -----------------
__global__ void k_trans(const float* __restrict__ Wmsg, const float* __restrict__ Wupd) {
    __shared__ float ts[32][33];
    const int b = blockIdx.x;
    const int tid = threadIdx.x;
    if (b < 96) {
        int mat = b >> 4;
        int tile = b & 15;
        int ti = tile >> 2, tj = tile & 3;
        int t_ = mat % 3, part = mat / 3;
        int rx = tid & 31, ry = tid >> 5;
#pragma unroll
        for (int p = 0; p < 4; p++) {
            int k = ti * 32 + ry + p * 8;
            ts[ry + p * 8][rx] = Wmsg[(t_ * 256 + part * 128 + k) * 128 + tj * 32 + rx];
        }
        __syncthreads();
#pragma unroll
        for (int p = 0; p < 4; p++) {
            int row = ry + p * 8;
            int kp = perm8(ti * 32 + rx);
            g_Wt[(part * 384 + t_ * 128 + tj * 32 + row) * 128 + kp] = ts[rx][row];
        }
    } else {
        int bb = b - 96;
        int ti = bb >> 2, tj = bb & 3;
        int rx = tid & 31, ry = tid >> 5;
#pragma unroll
        for (int p = 0; p < 4; p++)
            ts[ry + p * 8][rx] = Wupd[(ti * 32 + ry + p * 8) * 128 + tj * 32 + rx];
        __syncthreads();
#pragma unroll
        for (int p = 0; p < 4; p++) {
            int row = ry + p * 8;
            int kp = perm8(ti * 32 + rx);
            g_Wut[(tj * 32 + row) * 256 + kp] = ts[rx][row];
        }
    }
}

// ---------------- per-(dst,type) histogram ----------------
__global__ void k_hist(const int* __restrict__ ei, const int* __restrict__ et) {
    int e = blockIdx.x * blockDim.x + threadIdx.x;
    if (e >= N_EDGES) return;
    atomicAdd(&g_cnt[ei[N_EDGES + e] * 4 + et[e]], 1);
}

// ---------------- projection GEMM: A-in-regs, depth-2 double-buffered W ----------------------
__global__ void __launch_bounds__(512) k_proj(const float* __restrict__ x,
                                              const float* __restrict__ bmsg) {
    extern __shared__ float sm[];
    float* xs  = sm;                    // [128][APAD]
    float* wsb = sm + 128 * APAD;       // 2 x [64][BPAD]
    const int tid = threadIdx.x;
    const int n0 = blockIdx.x * 128;
    const uint32_t xs_b = (uint32_t)__cvta_generic_to_shared(xs);
    const uint32_t ws_b = (uint32_t)__cvta_generic_to_shared(wsb);

    for (int i = tid; i < 4096; i += 512) {
        int m = i >> 5, k4 = i & 31;
        int n = n0 + m;
        int sz = (n < N_NODES) ? 16 : 0;
        CPA16Z(xs_b + (m * APAD + k4 * 4) * 4, x + (size_t)n * 128 + k4 * 4, sz);
    }
    CPA_COMMIT();
    for (int i = tid; i < 2048; i += 512) {
        int r = i >> 5, k4 = i & 31;
        CPA16(ws_b + (r * BPAD + k4 * 4) * 4, g_Wt + r * 128 + k4 * 4);
    }
    CPA_COMMIT();

    const int w = tid >> 5, lane = tid & 31;
    const int gid = lane >> 2, tig = lane & 3;
    const int m0 = (w & 7) * 16;
    const int nw = (w >> 3) * 32;
    const int r0 = n0 + m0 + gid;

    CPA_WAIT(1);
    __syncthreads();
    uint32_t a[16][4];
    {
        const uint32_t* As = (const uint32_t*)xs;
#pragma unroll
        for (int ks = 0; ks < 16; ks++) {
            const uint32_t* ap = As + (m0 + gid) * APAD + ks * 8 + tig;
            a[ks][0] = ap[0];
            a[ks][1] = ap[8 * APAD];
            a[ks][2] = ap[4];
            a[ks][3] = ap[8 * APAD + 4];
        }
    }

    float accB[4][4];

    for (int idx = 0; idx < 12; idx++) {
        if (idx + 1 < 12) {
            uint32_t dst = ws_b + ((idx + 1) & 1) * 64 * BPAD * 4;
            const float* src = g_Wt + JT[idx + 1] * 64 * 128;
            for (int i = tid; i < 2048; i += 512) {
                int r = i >> 5, k4 = i & 31;
                CPA16(dst + (r * BPAD + k4 * 4) * 4, src + r * 128 + k4 * 4);
            }
            CPA_COMMIT();
            CPA_WAIT(1);
        } else {
            CPA_WAIT(0);
        }
        __syncthreads();

        const uint32_t* Ws = (const uint32_t*)(wsb + (idx & 1) * 64 * BPAD);

        float c[4][4];
#pragma unroll
        for (int nt = 0; nt < 4; nt++)
#pragma unroll
            for (int q = 0; q < 4; q++) c[nt][q] = 0.f;

#pragma unroll
        for (int ks = 0; ks < 16; ks++) {
#pragma unroll
            for (int nt = 0; nt < 4; nt++) {
                uint2 bv = *(const uint2*)(Ws + (nw + nt * 8 + gid) * BPAD + ks * 8 + tig * 2);
                uint32_t b[2] = {bv.x, bv.y};
                MMA_TF32(c[nt], a[ks], b);
            }
        }

        int j0 = JT[idx] * 64;
        if (j0 < 384) {
#pragma unroll
            for (int nt = 0; nt < 4; nt++) {
                int col = j0 + nw + nt * 8 + tig * 2;
                uint32_t p01 = pack_bf16(c[nt][0], c[nt][1]);
                uint32_t p23 = pack_bf16(c[nt][2], c[nt][3]);
                if (r0 < N_NODES)
                    g_Ah[(size_t)r0 * 192 + (col >> 1)] = p01;
                if (r0 + 8 < N_NODES)
                    g_Ah[(size_t)(r0 + 8) * 192 + (col >> 1)] = p23;
            }
        } else {
            int jj = j0 - 384;
            int t = jj >> 7;
            int h0 = jj & 127;
            float f0 = (r0 < N_NODES)     ? (float)g_cnt[r0 * 4 + t]       : 0.f;
            float f1 = (r0 + 8 < N_NODES) ? (float)g_cnt[(r0 + 8) * 4 + t] : 0.f;
#pragma unroll
            for (int nt = 0; nt < 4; nt++) {
                int hcol = h0 + nw + nt * 8 + tig * 2;
                float2 bm = *(const float2*)(bmsg + t * 128 + hcol);
                if (t == 0) { accB[nt][0] = 0.f; accB[nt][1] = 0.f; accB[nt][2] = 0.f; accB[nt][3] = 0.f; }
                accB[nt][0] += f0 * (c[nt][0] + bm.x);
                accB[nt][1] += f0 * (c[nt][1] + bm.y);
                accB[nt][2] += f1 * (c[nt][2] + bm.x);
                accB[nt][3] += f1 * (c[nt][3] + bm.y);
                if (t == 2) {
                    if (r0 < N_NODES)
                        *(float2*)(g_agg + (size_t)r0 * 128 + hcol) = make_float2(accB[nt][0], accB[nt][1]);
                    if (r0 + 8 < N_NODES)
                        *(float2*)(g_agg + (size_t)(r0 + 8) * 128 + hcol) = make_float2(accB[nt][2], accB[nt][3]);
                }
            }
        }
        __syncthreads();
    }
}

// ---------------- 2-phase parallel exclusive scan (block-local + block prefixes) -------------
__global__ void k_scan1() {
    __shared__ int wsum[32];
    const int tid = threadIdx.x, lane = tid & 31, wid = tid >> 5;
    int n = blockIdx.x * 1024 + tid;
    int v = 0;
    if (n < N_NODES) v = g_cnt[n * 4] + g_cnt[n * 4 + 1] + g_cnt[n * 4 + 2];
    int xv = v;
#pragma unroll
    for (int o = 1; o < 32; o <<= 1) {
        int y = __shfl_up_sync(0xffffffffu, xv, o);
        if (lane >= o) xv += y;
    }
    if (lane == 31) wsum[wid] = xv;
    __syncthreads();
    if (wid == 0) {
        int s = wsum[lane];
#pragma unroll
        for (int o = 1; o < 32; o <<= 1) {
            int y = __shfl_up_sync(0xffffffffu, s, o);
            if (lane >= o) s += y;
        }
        wsum[lane] = s;
    }
    __syncthreads();
    int excl = xv - v + (wid > 0 ? wsum[wid - 1] : 0);
    if (n < N_NODES) g_off[n] = excl;      // block-local exclusive prefix
    if (tid == 1023) g_bsum[blockIdx.x] = excl + v;
}

__global__ void k_scan2() {
    int run = 0;
    for (int b = 0; b < SCAN_BLOCKS; b++) {
        int t = g_bsum[b];
        g_bsum[b] = run;                   // exclusive block prefix
        run += t;
    }
}

// ---------------- CSR bucket fill (global offset = local + block prefix) ----------------
__global__ void k_fill(const int* __restrict__ ei, const int* __restrict__ et) {
    int e = blockIdx.x * blockDim.x + threadIdx.x;
    if (e >= N_EDGES) return;
    int dst = ei[N_EDGES + e];
    int p = atomicAdd(&g_pos[dst], 1);
    g_csr[g_off[dst] + g_bsum[dst >> 10] + p] = (ei[e] << 2) | et[e];
}

// ---------------- gather-aggregate (one warp per dst); 4 independent gathers in flight -------
__global__ void k_agg() {
    int n = (blockIdx.x * blockDim.x + threadIdx.x) >> 5;
    if (n >= N_NODES) return;
    int lane = threadIdx.x & 31;
    int beg = g_off[n] + g_bsum[n >> 10];
    int end = (n + 1 == N_NODES) ? N_EDGES : (g_off[n + 1] + g_bsum[(n + 1) >> 10]);
    int deg = end - beg;
    float4 a0 = ((const float4*)g_agg)[n * 32 + lane];   // cnt-weighted B + bias partial
    float4 a1 = make_float4(0.f, 0.f, 0.f, 0.f);
    float4 a2 = make_float4(0.f, 0.f, 0.f, 0.f);
    float4 a3 = make_float4(0.f, 0.f, 0.f, 0.f);
    const uint2* Ah = (const uint2*)g_Ah;

    int i = beg;
    for (; i + 4 <= end; i += 4) {
        int p0 = __ldg(&g_csr[i]);
        int p1 = __ldg(&g_csr[i + 1]);
        int p2 = __ldg(&g_csr[i + 2]);
        int p3 = __ldg(&g_csr[i + 3]);
        uint2 v0 = __ldg(Ah + (size_t)((p0 >> 2) * 3 + (p0 & 3)) * 32 + lane);
        uint2 v1 = __ldg(Ah + (size_t)((p1 >> 2) * 3 + (p1 & 3)) * 32 + lane);
        uint2 v2 = __ldg(Ah + (size_t)((p2 >> 2) * 3 + (p2 & 3)) * 32 + lane);
        uint2 v3 = __ldg(Ah + (size_t)((p3 >> 2) * 3 + (p3 & 3)) * 32 + lane);
        a0.x += bflo(v0.x); a0.y += bfhi(v0.x); a0.z += bflo(v0.y); a0.w += bfhi(v0.y);
        a1.x += bflo(v1.x); a1.y += bfhi(v1.x); a1.z += bflo(v1.y); a1.w += bfhi(v1.y);
        a2.x += bflo(v2.x); a2.y += bfhi(v2.x); a2.z += bflo(v2.y); a2.w += bfhi(v2.y);
        a3.x += bflo(v3.x); a3.y += bfhi(v3.x); a3.z += bflo(v3.y); a3.w += bfhi(v3.y);
    }
    for (; i < end; i++) {
        int p0 = __ldg(&g_csr[i]);
        uint2 v0 = __ldg(Ah + (size_t)((p0 >> 2) * 3 + (p0 & 3)) * 32 + lane);
        a0.x += bflo(v0.x); a0.y += bfhi(v0.x); a0.z += bflo(v0.y); a0.w += bfhi(v0.y);
    }
    a0.x += (a1.x + a2.x) + a3.x;
    a0.y += (a1.y + a2.y) + a3.y;
    a0.z += (a1.z + a2.z) + a3.z;
    a0.w += (a1.w + a2.w) + a3.w;
    float inv = 1.f / fmaxf((float)deg, 1.f);
    a0.x *= inv; a0.y *= inv; a0.z *= inv; a0.w *= inv;
    ((float4*)g_agg)[n * 32 + lane] = a0;
}

// ---------------- update GEMM: 512 threads, N-split warp tiles, smem LN exchange --------------
// 16 warps: warp w owns rows (w&7)*16..+15, column half (w>>3)*64..+63 (8 n-frags).
// LayerNorm stats per row are combined across the two column-half warps via smem.
// lnx region: [2][8][8][4] = 512 floats = 2048 bytes (sized correctly this time).
__global__ void __launch_bounds__(512) k_update(const float* __restrict__ x,
                                                const float* __restrict__ bupd,
                                                const float* __restrict__ gamma,
                                                const float* __restrict__ beta,
                                                float* __restrict__ out) {
    extern __shared__ float sm[];
    float* Is  = sm;                            // [128][APAD]
    float* Ws  = sm + 128 * APAD;               // [128][BPAD]
    float* lnx = sm + 128 * APAD + 128 * BPAD;  // [2][8][8][4] LN half-stats exchange (512 f)
    const int tid = threadIdx.x;
    const int n0 = blockIdx.x * 128;
    const uint32_t is_b = (uint32_t)__cvta_generic_to_shared(Is);
    const uint32_t ws_b = (uint32_t)__cvta_generic_to_shared(Ws);
    const int w = tid >> 5, lane = tid & 31;
    const int gid = lane >> 2, tig = lane & 3;
    const int wm = w & 7, ch = w >> 3;
    const int m0 = wm * 16;

    float c[8][4];
#pragma unroll
    for (int nt = 0; nt < 8; nt++)
#pragma unroll
        for (int q = 0; q < 4; q++) c[nt][q] = 0.f;

    for (int kt = 0; kt < 2; kt++) {
        const float* src = kt ? g_agg : x;
        for (int i = tid; i < 4096; i += 512) {
            int m = i >> 5, k4 = i & 31;
            int n = n0 + m;
            int sz = (n < N_NODES) ? 16 : 0;
            CPA16Z(is_b + (m * APAD + k4 * 4) * 4, src + (size_t)n * 128 + k4 * 4, sz);
        }
        for (int i = tid; i < 4096; i += 512) {
            int h = i >> 5, k4 = i & 31;
            CPA16(ws_b + (h * BPAD + k4 * 4) * 4, g_Wut + h * 256 + kt * 128 + k4 * 4);
        }
        CPA_COMMIT();
        CPA_WAIT(0);
        __syncthreads();

        const uint32_t* IsU = (const uint32_t*)Is;
        const uint32_t* WsU = (const uint32_t*)Ws;
#pragma unroll
        for (int ks = 0; ks < 16; ks++) {
            int kb = ks * 8;
            uint32_t a[4];
            const uint32_t* ap = IsU + (m0 + gid) * APAD + kb + tig;
            a[0] = ap[0];
            a[1] = ap[8 * APAD];
            a[2] = ap[4];
            a[3] = ap[8 * APAD + 4];
#pragma unroll
            for (int nt = 0; nt < 8; nt++) {
                uint2 bv = *(const uint2*)(WsU + (ch * 64 + nt * 8 + gid) * BPAD + kb + tig * 2);
                uint32_t b[2] = {bv.x, bv.y};
                MMA_TF32(c[nt], a, b);
            }
        }
        __syncthreads();
    }

    // Epilogue: bias, per-half LN partial stats (quad shfl), cross-half combine via smem.
    const int r0 = n0 + m0 + gid;
    const int r1 = r0 + 8;
    float s0 = 0.f, q0 = 0.f, s1 = 0.f, q1 = 0.f;
#pragma unroll
    for (int nt = 0; nt < 8; nt++) {
        int col = ch * 64 + nt * 8 + tig * 2;
        float2 bb = *(const float2*)(bupd + col);
        float h0 = c[nt][0] + bb.x, h1 = c[nt][1] + bb.y;
        float h2 = c[nt][2] + bb.x, h3 = c[nt][3] + bb.y;
        c[nt][0] = h0; c[nt][1] = h1; c[nt][2] = h2; c[nt][3] = h3;
        s0 += h0 + h1; q0 += h0 * h0 + h1 * h1;
        s1 += h2 + h3; q1 += h2 * h2 + h3 * h3;
    }
#pragma unroll
    for (int o = 1; o <= 2; o <<= 1) {
        s0 += __shfl_xor_sync(0xffffffffu, s0, o);
        q0 += __shfl_xor_sync(0xffffffffu, q0, o);
        s1 += __shfl_xor_sync(0xffffffffu, s1, o);
        q1 += __shfl_xor_sync(0xffffffffu, q1, o);
    }
    // exchange halves: lnx[ch][wm][gid][0..3]
    if (tig == 0) {
        float* p = lnx + ((ch * 8 + wm) * 8 + gid) * 4;
        p[0] = s0; p[1] = q0; p[2] = s1; p[3] = q1;
    }
    __syncthreads();
    {
        const float* p = lnx + (((ch ^ 1) * 8 + wm) * 8 + gid) * 4;
        s0 += p[0]; q0 += p[1]; s1 += p[2]; q1 += p[3];
    }
    const float inv_h = 1.f / 128.f;
    float mu0 = s0 * inv_h, var0 = q0 * inv_h - mu0 * mu0;
    float mu1 = s1 * inv_h, var1 = q1 * inv_h - mu1 * mu1;
    float rs0 = rsqrtf(var0 + LN_EPS);
    float rs1 = rsqrtf(var1 + LN_EPS);
    const float inv_sqrt2 = 0.70710678118654752f;

#pragma unroll
    for (int nt = 0; nt < 8; nt++) {
        int col = ch * 64 + nt * 8 + tig * 2;
        float2 gg = *(const float2*)(gamma + col);
        float2 be = *(const float2*)(beta + col);
        if (r0 < N_NODES) {
            float2 xv = *(const float2*)(x + (size_t)r0 * HIDDEN + col);
            float hn0 = (c[nt][0] - mu0) * rs0 * gg.x + be.x;
            float hn1 = (c[nt][1] - mu0) * rs0 * gg.y + be.y;
            float g0 = 0.5f * hn0 * (1.f + erff(hn0 * inv_sqrt2));
            float g1 = 0.5f * hn1 * (1.f + erff(hn1 * inv_sqrt2));
            *(float2*)(out + (size_t)r0 * HIDDEN + col) = make_float2(xv.x + g0, xv.y + g1);
        }
        if (r1 < N_NODES) {
            float2 xv = *(const float2*)(x + (size_t)r1 * HIDDEN + col);
            float hn2 = (c[nt][2] - mu1) * rs1 * gg.x + be.x;
            float hn3 = (c[nt][3] - mu1) * rs1 * gg.y + be.y;
            float g2 = 0.5f * hn2 * (1.f + erff(hn2 * inv_sqrt2));
            float g3 = 0.5f * hn3 * (1.f + erff(hn3 * inv_sqrt2));
            *(float2*)(out + (size_t)r1 * HIDDEN + col) = make_float2(xv.x + g2, xv.y + g3);
        }
    }
}

extern "C" void kernel_launch(void* const* d_in, const int* in_sizes, int n_in,
                              void* d_out, int out_size) {
    const float* x     = (const float*)d_in[0];
    const int*   ei    = (const int*)d_in[1];
    const int*   et    = (const int*)d_in[2];
    const float* Wmsg  = (const float*)d_in[3];
    const float* bmsg  = (const float*)d_in[4];
    const float* Wupd  = (const float*)d_in[5];
    const float* bupd  = (const float*)d_in[6];
    const float* gamma = (const float*)d_in[7];
    const float* beta  = (const float*)d_in[8];
    float* out = (float*)d_out;

    // One-time streams + events (host objects; created outside capture on first call).
    static cudaStream_t s2 = nullptr, s3 = nullptr;
    static cudaEvent_t ev0 = nullptr, ev_fork = nullptr, ev_join = nullptr, ev_t = nullptr;
    if (s2 == nullptr) {
        cudaStreamCreateWithFlags(&s2, cudaStreamNonBlocking);
        cudaStreamCreateWithFlags(&s3, cudaStreamNonBlocking);
        cudaEventCreateWithFlags(&ev0, cudaEventDisableTiming);
        cudaEventCreateWithFlags(&ev_fork, cudaEventDisableTiming);
        cudaEventCreateWithFlags(&ev_join, cudaEventDisableTiming);
        cudaEventCreateWithFlags(&ev_t, cudaEventDisableTiming);
    }

    const int PROJ_SM = (128 * APAD + 2 * 64 * BPAD) * 4;          // 137216 B
    const int UPD_SM  = (128 * APAD + 128 * BPAD) * 4 + 512 * 4;   // 139264 B (lnx = 512 floats)
    cudaFuncSetAttribute(k_proj,   cudaFuncAttributeMaxDynamicSharedMemorySize, PROJ_SM);
    cudaFuncSetAttribute(k_update, cudaFuncAttributeMaxDynamicSharedMemorySize, UPD_SM);

    // s3: weight transposes, concurrent with zero+hist on main
    cudaEventRecord(ev0, 0);
    cudaStreamWaitEvent(s3, ev0, 0);
    k_trans<<<128, 256, 0, s3>>>(Wmsg, Wupd);
    cudaEventRecord(ev_t, s3);

    k_zero<<<64, 256>>>();
    k_hist<<<(N_EDGES + 255) / 256, 256>>>(ei, et);

    // s2: CSR build (scan1 -> scan2 -> fill), concurrent with k_proj on main
    cudaEventRecord(ev_fork, 0);
    cudaStreamWaitEvent(s2, ev_fork, 0);
    k_scan1<<<SCAN_BLOCKS, 1024, 0, s2>>>();
    k_scan2<<<1, 1, 0, s2>>>();
    k_fill<<<(N_EDGES + 255) / 256, 256, 0, s2>>>(ei, et);
    cudaEventRecord(ev_join, s2);

    // proj needs g_Wt (s3) + g_cnt (hist, main)
    cudaStreamWaitEvent(0, ev_t, 0);
    k_proj<<<(N_NODES + 127) / 128, 512, PROJ_SM>>>(x, bmsg);

    // agg needs proj (g_Ah, g_agg partial) + fill (g_csr)
    cudaStreamWaitEvent(0, ev_join, 0);
    k_agg<<<(N_NODES + 7) / 8, 256>>>();

    k_update<<<(N_NODES + 127) / 128, 512, UPD_SM>>>(x, bupd, gamma, beta, out);
}